// round 17
// baseline (speedup 1.0000x reference)
#include <cuda_runtime.h>
#include <cuda_fp16.h>
#include <cstdint>

// ---------------- problem constants ----------------
#define BB   2048      // batch
#define LL   64        // words / sentence
#define DD   300       // embedding dim (K of encoder GEMM)
#define CC   512       // conv out channels
#define HH   2048      // fc hidden
// encoder GEMM: M = BB*LL = 131072, N = CC = 512, K = 300 (padded 320)
// fc1 GEMM:     M = BB = 2048,     N = HH = 2048, K = 2*CC = 1024

#define WC2  160       // Wc half-image row stride in half2 (320 halfs, zero-padded)
#define W12  512       // W1 half-image row stride in half2 (1024 halfs)

// ---------------- scratch (no allocations allowed) ----------------
__device__ float    g_e[2 * BB * CC];            // e1 | e2   (8 MB)
__device__ float    g_h[(size_t)BB * HH];        // tanh hidden (16 MB)
__device__ uint32_t g_wh[CC * WC2];              // half image of Wc (0.3 MB)
__device__ uint32_t g_w1h[(size_t)HH * W12];     // half image of W1 (4 MB)
__device__ uint32_t g_fh[(size_t)BB * 512];      // half image of feat (4 MB)

// ---------------- helpers ----------------
__device__ __forceinline__ uint32_t pk2(float a, float b) {
    __half2 h = __floats2half2_rn(a, b);     // memory order [h(a), h(b)]
    return *(uint32_t*)&h;
}

__device__ __forceinline__ void mma_f16(float c[4], const uint32_t a[4], const uint32_t b[2]) {
    asm volatile(
        "mma.sync.aligned.m16n8k16.row.col.f32.f16.f16.f32 "
        "{%0,%1,%2,%3}, {%4,%5,%6,%7}, {%8,%9}, {%0,%1,%2,%3};"
        : "+f"(c[0]), "+f"(c[1]), "+f"(c[2]), "+f"(c[3])
        : "r"(a[0]), "r"(a[1]), "r"(a[2]), "r"(a[3]), "r"(b[0]), "r"(b[1]));
}

__device__ __forceinline__ void cpa16(uint32_t dst, const void* src) {
    asm volatile("cp.async.cg.shared.global [%0], [%1], 16;"
                 :: "r"(dst), "l"(src));
}
__device__ __forceinline__ void cpa_commit() {
    asm volatile("cp.async.commit_group;");
}

// =====================================================================
// ENCODE geometry: CTA = 128 words (2 sentences) x 512 channels.
// A (x tile, full K=320 halfs) resident in smem; B streamed per K-tile.
// 8 warps: wm = warp&1 (sentence strip of 64 rows), wn = warp>>1 (64-ch strip
// of the current 256-channel block); 2 channel blocks sequential.
// =====================================================================
#define ASTR  164                      // A slab row stride (half2): 160 data + 4 pad
#define ASLAB (128 * ASTR)             // 20992 half2 = 83968 B
#define EBSTR 20                       // B stage row stride (half2)
#define EBST  (256 * EBSTR)            // one B stage: 256 ch x 16 half2(+pad)
#define ENC_SMEM ((ASLAB + 2 * EBST) * 4)   // 83968 + 40960 = 124928 B

// fc1 tiling (CTA 256 x 128, both operands cp.async raw half)
#define SPW   20
#define ASW   (256 * SPW)
#define BSW   (128 * SPW)
#define FC1_SMEM ((2 * (ASW + BSW)) * 4)    // 61440 B

// ---------------- compute: A from resident slab, B from stage ----------------
template <int NSTEP>
__device__ __forceinline__ void compute_slab(const uint32_t* __restrict__ As,
                                             const uint32_t* __restrict__ Bs,
                                             int kcol,   // half2 col of this K-tile
                                             int wm, int wn, int g, int tg,
                                             float acc[4][8][4])
{
    #pragma unroll
    for (int s = 0; s < NSTEP; s++) {
        uint32_t a[4][4], b[8][2];
        #pragma unroll
        for (int f = 0; f < 4; f++) {
            int r = wm * 64 + f * 16;
            a[f][0] = As[(r + g    ) * ASTR + kcol + s * 8 + tg    ];
            a[f][1] = As[(r + g + 8) * ASTR + kcol + s * 8 + tg    ];
            a[f][2] = As[(r + g    ) * ASTR + kcol + s * 8 + tg + 4];
            a[f][3] = As[(r + g + 8) * ASTR + kcol + s * 8 + tg + 4];
        }
        #pragma unroll
        for (int ni = 0; ni < 8; ni++) {
            int c = wn * 64 + ni * 8;
            b[ni][0] = Bs[(c + g) * EBSTR + s * 8 + tg    ];
            b[ni][1] = Bs[(c + g) * EBSTR + s * 8 + tg + 4];
        }
        #pragma unroll
        for (int f = 0; f < 4; f++)
            #pragma unroll
            for (int ni = 0; ni < 8; ni++)
                mma_f16(acc[f][ni], a[f], b[ni]);
    }
}

// ---------------- compute: both staged (fc1), stride SPW ----------------
template <int NSTEP>
__device__ __forceinline__ void compute_tile(const uint32_t* __restrict__ As,
                                             const uint32_t* __restrict__ Bs,
                                             int wm, int wn, int g, int tg,
                                             float acc[4][8][4])
{
    #pragma unroll
    for (int s = 0; s < NSTEP; s++) {
        const int kk = s * 8;
        uint32_t a[4][4], b[8][2];
        #pragma unroll
        for (int f = 0; f < 4; f++) {
            int r = wm * 64 + f * 16;
            a[f][0] = As[(r + g    ) * SPW + kk + tg    ];
            a[f][1] = As[(r + g + 8) * SPW + kk + tg    ];
            a[f][2] = As[(r + g    ) * SPW + kk + tg + 4];
            a[f][3] = As[(r + g + 8) * SPW + kk + tg + 4];
        }
        #pragma unroll
        for (int ni = 0; ni < 8; ni++) {
            int c = wn * 64 + ni * 8;
            b[ni][0] = Bs[(c + g) * SPW + kk + tg    ];
            b[ni][1] = Bs[(c + g) * SPW + kk + tg + 4];
        }
        #pragma unroll
        for (int f = 0; f < 4; f++)
            #pragma unroll
            for (int ni = 0; ni < 8; ni++)
                mma_f16(acc[f][ni], a[f], b[ni]);
    }
}

// =====================================================================
// Kernel 0a/0b: one-time half images of the weights
// =====================================================================
__global__ __launch_bounds__(256)
void cvt_wc_kernel(const float* __restrict__ Wc)
{
    int idx = blockIdx.x * 256 + threadIdx.x;
    if (idx >= CC * WC2) return;
    int row = idx / WC2, c2 = idx % WC2;
    int k0 = c2 * 2, k1 = k0 + 1;
    float f0 = (k0 < DD) ? Wc[(size_t)row * DD + k0] : 0.f;
    float f1 = (k1 < DD) ? Wc[(size_t)row * DD + k1] : 0.f;
    g_wh[idx] = pk2(f0, f1);
}

__global__ __launch_bounds__(256)
void cvt_w1_kernel(const float* __restrict__ W1)
{
    size_t idx = (size_t)blockIdx.x * 256 + threadIdx.x;  // half2 index
    float2 v = *(const float2*)(W1 + idx * 2);
    g_w1h[idx] = pk2(v.x, v.y);
}

// =====================================================================
// Kernel 1: encoder.  grid = (1024 word-tiles, 2 inputs), block = 256
// relu(max_L(x @ Wc^T) + bc) folded into per-channel-block epilogue.
// =====================================================================
__global__ __launch_bounds__(256, 1)
void encode_kernel(const float* __restrict__ x1, const float* __restrict__ x2,
                   const float* __restrict__ bc)
{
    extern __shared__ uint32_t sh[];
    uint32_t sbase = (uint32_t)__cvta_generic_to_shared(sh);
    uint32_t* __restrict__ Aslab = sh;                    // 128 x ASTR

    const float* __restrict__ x = (blockIdx.y == 0) ? x1 : x2;
    const int mbase = blockIdx.x * 128;

    const int tid  = threadIdx.x;
    const int warp = tid >> 5, lane = tid & 31;
    const int wm = warp & 1;       // sentence strip (64 rows)
    const int wn = warp >> 1;      // 64-channel strip within 256-ch block
    const int g  = lane >> 2, tg = lane & 3;

    // ---- prologue: x tile (128 rows x 300 fp32) -> half slab, zero-padded ----
    {
        const int row  = tid >> 1;
        const int half = tid & 1;
        const float* __restrict__ src = x + (size_t)(mbase + row) * DD;
        uint32_t* __restrict__ drow = Aslab + row * ASTR;
        if (half == 0) {
            #pragma unroll 8
            for (int i = 0; i < 40; i++) {           // k = 0..159
                float4 v = *(const float4*)(src + i * 4);
                drow[i * 2    ] = pk2(v.x, v.y);
                drow[i * 2 + 1] = pk2(v.z, v.w);
            }
        } else {
            #pragma unroll 7
            for (int i = 0; i < 35; i++) {           // k = 160..299
                float4 v = *(const float4*)(src + 160 + i * 4);
                drow[80 + i * 2    ] = pk2(v.x, v.y);
                drow[80 + i * 2 + 1] = pk2(v.z, v.w);
            }
            #pragma unroll
            for (int i = 0; i < 10; i++)             // halfs 300..319 = 0
                drow[150 + i] = 0u;
        }
    }

    // B stage loader: 256 ch x 16 half2 per K-tile, 4 cp16/thread
    auto cpB = [&](int buf, int nb, int kt) {
        #pragma unroll
        for (int it = 0; it < 4; it++) {
            int id  = tid + it * 256;
            int row = id >> 2;                       // channel within block
            int col = (id & 3) * 4;                  // half2 offset
            const uint32_t* src = g_wh + (size_t)(nb * 256 + row) * WC2 + kt * 16 + col;
            uint32_t dst = sbase + (uint32_t)(ASLAB + buf * EBST + row * EBSTR + col) * 4u;
            cpa16(dst, src);
        }
    };

    float acc[4][8][4] = {};

    // prime stage 0 with (nb=0, kt=0); the sync also publishes the A slab
    cpB(0, 0, 0);
    cpa_commit();
    asm volatile("cp.async.wait_group 0;");
    __syncthreads();

    #pragma unroll 1
    for (int t = 0; t < 20; t++) {                   // t = nb*10 + kt
        const int kt = (t < 10) ? t : t - 10;
        if (t + 1 < 20) {
            const int t1 = t + 1;
            cpB(t1 & 1, (t1 < 10) ? 0 : 1, (t1 < 10) ? t1 : t1 - 10);
            cpa_commit();
        }

        const uint32_t* Bs = sh + ASLAB + (t & 1) * EBST;
        if (kt == 9)    // k16-step 288..303 covers the 300 real columns
            compute_slab<1>(Aslab, Bs, kt * 16, wm, wn, g, tg, acc);
        else
            compute_slab<2>(Aslab, Bs, kt * 16, wm, wn, g, tg, acc);

        if (kt == 9) {
            // ---- epilogue for this 256-channel block ----
            const int nb = (t < 10) ? 0 : 1;
            const size_t sent = (size_t)blockIdx.x * 2 + wm;
            const int cbase = nb * 256 + wn * 64;
            float* __restrict__ eout =
                g_e + ((size_t)blockIdx.y * BB + sent) * CC + cbase;
            #pragma unroll
            for (int ni = 0; ni < 8; ni++) {
                #pragma unroll
                for (int j = 0; j < 2; j++) {
                    float m = -3.4e38f;
                    #pragma unroll
                    for (int f = 0; f < 4; f++)
                        m = fmaxf(m, fmaxf(acc[f][ni][j], acc[f][ni][j + 2]));
                    #pragma unroll
                    for (int off = 4; off < 32; off <<= 1)
                        m = fmaxf(m, __shfl_xor_sync(0xffffffffu, m, off));
                    if (g == 0) {
                        int col = ni * 8 + 2 * tg + j;
                        eout[col] = fmaxf(m + bc[cbase + col], 0.f);
                    }
                }
            }
            #pragma unroll
            for (int f = 0; f < 4; f++)
                #pragma unroll
                for (int ni = 0; ni < 8; ni++)
                    #pragma unroll
                    for (int q = 0; q < 4; q++)
                        acc[f][ni][q] = 0.f;
        }

        if (t + 1 < 20) {
            asm volatile("cp.async.wait_group 0;");
            __syncthreads();
        }
    }
}

// =====================================================================
// Kernel 2: feat half image: g_fh[b][j] = (e1-e2 | e1*e2) as half
// =====================================================================
__global__ __launch_bounds__(256)
void feat_kernel()
{
    int idx = blockIdx.x * 256 + threadIdx.x;        // half2 index, BB*512 total
    int row = idx >> 9;
    int j   = (idx & 511) * 2;                       // feat column (0..1022, even)
    const float* __restrict__ e1 = g_e;
    const float* __restrict__ e2 = g_e + (size_t)BB * CC;
    uint32_t v;
    if (j < CC) {
        float2 p = *(const float2*)(e1 + (size_t)row * CC + j);
        float2 q = *(const float2*)(e2 + (size_t)row * CC + j);
        v = pk2(p.x - q.x, p.y - q.y);
    } else {
        int j2 = j - CC;
        float2 p = *(const float2*)(e1 + (size_t)row * CC + j2);
        float2 q = *(const float2*)(e2 + (size_t)row * CC + j2);
        v = pk2(p.x * q.x, p.y * q.y);
    }
    g_fh[idx] = v;
}

// =====================================================================
// Kernel 3: FC1.  grid = (H/128, B/256), block = 256
// Both operands cp.async raw half.  h = tanh(feat @ W1^T + b1)
// =====================================================================
__global__ __launch_bounds__(256, 1)
void fc1_kernel(const float* __restrict__ b1)
{
    extern __shared__ uint32_t sh[];
    uint32_t sbase = (uint32_t)__cvta_generic_to_shared(sh);

    const int mbase = blockIdx.y * 256;
    const int nbase = blockIdx.x * 128;

    const int tid  = threadIdx.x;
    const int warp = tid >> 5, lane = tid & 31;
    const int wm = warp >> 1, wn = warp & 1;
    const int g  = lane >> 2, tg = lane & 3;

    auto cpA = [&](int buf, int kt) {
        #pragma unroll
        for (int it = 0; it < 4; it++) {
            int id  = tid + it * 256;
            int row = id >> 2;
            int col = (id & 3) * 4;
            const uint32_t* src = g_fh + (size_t)(mbase + row) * 512 + kt * 16 + col;
            uint32_t dst = sbase + (uint32_t)(buf * ASW + row * SPW + col) * 4u;
            cpa16(dst, src);
        }
    };
    auto cpB = [&](int buf, int kt) {
        #pragma unroll
        for (int it = 0; it < 2; it++) {
            int id  = tid + it * 256;
            int row = id >> 2;
            int col = (id & 3) * 4;
            const uint32_t* src = g_w1h + (size_t)(nbase + row) * W12 + kt * 16 + col;
            uint32_t dst = sbase + (uint32_t)(2 * ASW + buf * BSW + row * SPW + col) * 4u;
            cpa16(dst, src);
        }
    };

    float acc[4][8][4] = {};

    const int NK = 32;     // K tiles of 32 halfs
    cpA(0, 0);
    cpB(0, 0);
    cpa_commit();
    asm volatile("cp.async.wait_group 0;");
    __syncthreads();

    #pragma unroll 1
    for (int i = 0; i < NK; i++) {
        if (i + 1 < NK) {
            cpA((i + 1) & 1, i + 1);
            cpB((i + 1) & 1, i + 1);
            cpa_commit();
        }

        const uint32_t* As = sh + (i & 1) * ASW;
        const uint32_t* Bs = sh + 2 * ASW + (i & 1) * BSW;
        compute_tile<2>(As, Bs, wm, wn, g, tg, acc);

        if (i + 1 < NK) {
            asm volatile("cp.async.wait_group 0;");
            __syncthreads();
        }
    }

    // epilogue: bias + tanh, direct store
    #pragma unroll
    for (int f = 0; f < 4; f++) {
        #pragma unroll
        for (int ni = 0; ni < 8; ni++) {
            #pragma unroll
            for (int q = 0; q < 4; q++) {
                int row = mbase + wm * 64 + f * 16 + g + ((q >> 1) ? 8 : 0);
                int col = nbase + wn * 64 + ni * 8 + 2 * tg + (q & 1);
                g_h[(size_t)row * HH + col] = tanhf(acc[f][ni][q] + b1[col]);
            }
        }
    }
}

// =====================================================================
// Kernel 4: FC2 (H -> 1), fp32, float4 loads.  grid = B, block = 256
// =====================================================================
__global__ __launch_bounds__(256)
void fc2_kernel(const float* __restrict__ W2, const float* __restrict__ b2,
                float* __restrict__ out)
{
    const int b = blockIdx.x;
    const float4* __restrict__ h4 = (const float4*)(g_h + (size_t)b * HH);
    const float4* __restrict__ w4 = (const float4*)W2;
    float s = 0.f;
    #pragma unroll
    for (int i = 0; i < 2; i++) {
        int idx = threadIdx.x + i * 256;
        float4 hv = h4[idx], wv = w4[idx];
        s += hv.x * wv.x + hv.y * wv.y + hv.z * wv.z + hv.w * wv.w;
    }
    #pragma unroll
    for (int off = 16; off > 0; off >>= 1)
        s += __shfl_xor_sync(0xffffffffu, s, off);
    __shared__ float sm[8];
    int warp = threadIdx.x >> 5, lane = threadIdx.x & 31;
    if (lane == 0) sm[warp] = s;
    __syncthreads();
    if (warp == 0) {
        float v = (lane < 8) ? sm[lane] : 0.f;
        #pragma unroll
        for (int off = 4; off > 0; off >>= 1)
            v += __shfl_xor_sync(0xffffffffu, v, off);
        if (lane == 0) out[b] = v + b2[0];
    }
}

// =====================================================================
extern "C" void kernel_launch(void* const* d_in, const int* in_sizes, int n_in,
                              void* d_out, int out_size)
{
    (void)in_sizes; (void)n_in; (void)out_size;
    const float* x1 = (const float*)d_in[0];
    const float* x2 = (const float*)d_in[1];
    const float* Wc = (const float*)d_in[2];
    const float* bc = (const float*)d_in[3];
    const float* W1 = (const float*)d_in[4];
    const float* b1 = (const float*)d_in[5];
    const float* W2 = (const float*)d_in[6];
    const float* b2 = (const float*)d_in[7];
    float* out = (float*)d_out;

    static bool attr_done = false;
    if (!attr_done) {
        cudaFuncSetAttribute(encode_kernel,
                             cudaFuncAttributeMaxDynamicSharedMemorySize, ENC_SMEM);
        cudaFuncSetAttribute(fc1_kernel,
                             cudaFuncAttributeMaxDynamicSharedMemorySize, FC1_SMEM);
        attr_done = true;
    }

    // one-time-per-launch half weight images (~8us total)
    cvt_wc_kernel<<<(CC * WC2 + 255) / 256, 256>>>(Wc);
    cvt_w1_kernel<<<((HH * W12) + 255) / 256, 256>>>(W1);

    dim3 g1((BB * LL) / 128, 2);                   // 1024 x 2 = 2048 CTAs
    encode_kernel<<<g1, 256, ENC_SMEM>>>(x1, x2, bc);

    feat_kernel<<<(BB * 512) / 256, 256>>>();      // 4096 CTAs

    dim3 g2(HH / 128, BB / 256);                   // 16 x 8 = 128 CTAs
    fc1_kernel<<<g2, 256, FC1_SMEM>>>(b1);

    fc2_kernel<<<BB, 256>>>(W2, b2, out);
}